// round 2
// baseline (speedup 1.0000x reference)
#include <cuda_runtime.h>

#define HWD   96
#define NVOX  (96*96*96)        /* 884736 voxels per volume   */
#define NVOL  8                 /* 4 pred + 4 target volumes  */
#define NTOT  (NVOX*NVOL)       /* 7077888                    */
#define NELEM (4*NVOX)          /* elements per input tensor  */

// scratch (device globals: allocation-free per harness rules)
__device__ int            g_label[NTOT];
__device__ unsigned char  g_fg[NTOT];
__device__ double         g_focal;
__device__ int            g_counts[NVOL];

// ---------------------------------------------------------------------------
// zero accumulators (must precede the fused init/focal kernel's atomics)
// ---------------------------------------------------------------------------
__global__ void k_zero()
{
    if (threadIdx.x == 0) g_focal = 0.0;
    if (threadIdx.x < NVOL) g_counts[threadIdx.x] = 0;
}

// ---------------------------------------------------------------------------
// fused: fg masks + x-run chain labels (both volume sets) + focal reduction
// one thread per input element; handles pred-volume voxel idx and
// target-volume voxel idx+NELEM.
// ---------------------------------------------------------------------------
__global__ void k_init_focal(const float* __restrict__ pred,
                             const float* __restrict__ tgt)
{
    int idx = blockIdx.x * blockDim.x + threadIdx.x;
    double v = 0.0;
    if (idx < NELEM) {
        float x = pred[idx];
        float t = tgt[idx];
        int   d = idx % HWD;                 // D = innermost (stride-1) axis
        bool fgp = x > 0.0f;                 // sigmoid(x)>0.5 <=> x>0
        bool fgt = t > 0.5f;
        bool fgp_prev = false, fgt_prev = false;
        if (d > 0) {
            fgp_prev = pred[idx-1] > 0.0f;   // L1 hit (same line mostly)
            fgt_prev = tgt[idx-1]  > 0.5f;
        }
        g_fg[idx]           = fgp ? 1 : 0;
        g_fg[idx + NELEM]   = fgt ? 1 : 0;
        g_label[idx]         = (fgp && fgp_prev) ? (idx - 1)         : idx;
        g_label[idx + NELEM] = (fgt && fgt_prev) ? (idx + NELEM - 1) : (idx + NELEM);

        // focal term (numerically stable BCE-with-logits)
        float sp  = fmaxf(x, 0.0f) + log1pf(expf(-fabsf(x)));
        float bce = sp - x * t;
        float p   = 1.0f / (1.0f + expf(-x));
        bool  one = t > 0.5f;
        float pt  = one ? p : 1.0f - p;
        float at  = one ? 0.25f : 0.75f;
        float om  = 1.0f - pt;
        v = (double)(at * om * om * bce);
    }
    // block reduce -> one atomicAdd per block
    #pragma unroll
    for (int off = 16; off > 0; off >>= 1)
        v += __shfl_down_sync(0xffffffffu, v, off);
    __shared__ double s[8];
    int lane = threadIdx.x & 31, w = threadIdx.x >> 5;
    if (lane == 0) s[w] = v;
    __syncthreads();
    if (w == 0) {
        v = (lane < (blockDim.x >> 5)) ? s[lane] : 0.0;
        #pragma unroll
        for (int off = 4; off > 0; off >>= 1)
            v += __shfl_down_sync(0xffffffffu, v, off);
        if (lane == 0) atomicAdd(&g_focal, v);
    }
}

// ---------------------------------------------------------------------------
// ECL-CC style find with path compression.
// Labels are monotone non-increasing; plain stores race-safely shorten paths
// (a successful atomicMin hook requires label[r]==r, which can never recur
// once the slot has been observed non-root).
// ---------------------------------------------------------------------------
__device__ __forceinline__ int rep(int v)
{
    int curr = g_label[v];
    if (curr != v) {
        int prev = v, next;
        while (curr > (next = g_label[curr])) {
            g_label[prev] = next;    // path compression (monotone store)
            prev = curr;
            curr = next;
        }
    }
    return curr;
}

__device__ __forceinline__ void unite(int a, int b)
{
    int ra = rep(a);
    int rb = rep(b);
    while (ra != rb) {
        if (ra > rb) { int t = ra; ra = rb; rb = t; }  // hook larger -> smaller
        int old = atomicMin(&g_label[rb], ra);
        if (old == rb) return;        // rb was root: hooked, done
        rb = rep(old);                // lost race: keep uniting ra with old
    }
}

// ---------------------------------------------------------------------------
// merge along +W and +H; skip unions whose run-pair was already emitted by
// the previous voxel along D (contact-segment start only)
// ---------------------------------------------------------------------------
__global__ void k_merge()
{
    int idx = blockIdx.x * blockDim.x + threadIdx.x;
    if (idx >= NTOT) return;
    if (!g_fg[idx]) return;
    int loc = idx % NVOX;
    int d   = loc % HWD;
    int w   = (loc / HWD) % HWD;
    int h   = loc / (HWD * HWD);
    bool prev_fg = (d > 0) && g_fg[idx - 1];

    if (w < HWD-1 && g_fg[idx + HWD]) {
        if (!(prev_fg && g_fg[idx + HWD - 1]))       // segment start only
            unite(idx, idx + HWD);
    }
    if (h < HWD-1 && g_fg[idx + HWD*HWD]) {
        if (!(prev_fg && g_fg[idx + HWD*HWD - 1]))
            unite(idx, idx + HWD*HWD);
    }
}

// ---------------------------------------------------------------------------
// count roots per volume (block fully inside one volume: NVOX % 256 == 0)
// ---------------------------------------------------------------------------
__global__ void k_count()
{
    int idx = blockIdx.x * 256 + threadIdx.x;
    int c = (g_fg[idx] && g_label[idx] == idx) ? 1 : 0;
    int wsum = __popc(__ballot_sync(0xffffffffu, c));
    __shared__ int s;
    if (threadIdx.x == 0) s = 0;
    __syncthreads();
    if ((threadIdx.x & 31) == 0 && wsum) atomicAdd(&s, wsum);
    __syncthreads();
    if (threadIdx.x == 0 && s > 0)
        atomicAdd(&g_counts[blockIdx.x / (NVOX/256)], s);
}

// ---------------------------------------------------------------------------
// final combine
// ---------------------------------------------------------------------------
__global__ void k_final(float* __restrict__ out)
{
    // volumes in reshape(B*C): v = b*C + c with B=2, C=2
    float c0 = (float)g_counts[0], c1 = (float)g_counts[1];
    float c2 = (float)g_counts[2], c3 = (float)g_counts[3];
    float t0 = (float)g_counts[4], t1 = (float)g_counts[5];
    float t2 = (float)g_counts[6], t3 = (float)g_counts[7];
    float ccp0 = 0.5f*(c0 + c2), ccp1 = 0.5f*(c1 + c3);   // mean over batch
    float cct0 = 0.5f*(t0 + t2), cct1 = 0.5f*(t1 + t3);
    float topo = 0.5f*(fabsf(ccp0 - cct0) + fabsf(ccp1 - cct1)); // mean over C
    float focal = (float)(g_focal / (double)NELEM);
    out[0] = focal + 0.1f * topo;
}

// ---------------------------------------------------------------------------
extern "C" void kernel_launch(void* const* d_in, const int* in_sizes, int n_in,
                              void* d_out, int out_size)
{
    const float* pred = (const float*)d_in[0];
    const float* tgt  = (const float*)d_in[1];
    float*       out  = (float*)d_out;

    const int T = 256;
    k_zero      <<<1, 32>>>();
    k_init_focal<<<(NELEM + T-1)/T, T>>>(pred, tgt);
    k_merge     <<<(NTOT  + T-1)/T, T>>>();
    k_count     <<<NTOT/T, T>>>();
    k_final     <<<1, 1>>>(out);
}

// round 3
// speedup vs baseline: 2.2963x; 2.2963x over previous
#include <cuda_runtime.h>

#define HWD   96
#define NVOX  (96*96*96)        /* 884736 voxels per volume   */
#define NVOL  8                 /* 4 pred + 4 target volumes  */
#define NTOT  (NVOX*NVOL)       /* 7077888                    */
#define NELEM (4*NVOX)          /* elements per input tensor  */

#define TW 8                    /* tile width  (W axis)       */
#define TH 8                    /* tile height (H axis)       */
#define TVOX (HWD*TW*TH)        /* 6144 voxels per tile       */
#define TILES_W (HWD/TW)        /* 12 */
#define TILES_H (HWD/TH)        /* 12 */
#define TILES_PER_VOL (TILES_W*TILES_H)  /* 144 */
#define NBLK_LOCAL (NVOL*TILES_PER_VOL)  /* 1152 */

// scratch (device globals: allocation-free per harness rules)
__device__ int            g_label[NTOT];
__device__ unsigned char  g_fg[NTOT];
__device__ double         g_focal;
__device__ int            g_counts[NVOL];

// ---------------------------------------------------------------------------
__global__ void k_zero()
{
    if (threadIdx.x == 0) g_focal = 0.0;
    if (threadIdx.x < NVOL) g_counts[threadIdx.x] = 0;
}

// ---------------------------------------------------------------------------
// fused fg computation (both tensors) + focal reduction; float4 vectorized
// ---------------------------------------------------------------------------
__global__ void k_init_focal(const float4* __restrict__ pred,
                             const float4* __restrict__ tgt)
{
    int i4 = blockIdx.x * blockDim.x + threadIdx.x;   // NELEM/4 threads
    double acc = 0.0;
    if (i4 < NELEM/4) {
        float4 x4 = pred[i4];
        float4 t4 = tgt[i4];
        const float* xs = &x4.x;
        const float* ts = &t4.x;
        unsigned int fgp = 0, fgt = 0;
        float fsum = 0.0f;
        #pragma unroll
        for (int k = 0; k < 4; ++k) {
            float x = xs[k], t = ts[k];
            bool bp = x > 0.0f;       // sigmoid(x)>0.5 <=> x>0
            bool bt = t > 0.5f;
            fgp |= (bp ? 1u : 0u) << (8*k);
            fgt |= (bt ? 1u : 0u) << (8*k);
            float sp  = fmaxf(x, 0.0f) + log1pf(expf(-fabsf(x)));
            float bce = sp - x * t;
            float p   = 1.0f / (1.0f + expf(-x));
            float pt  = bt ? p : 1.0f - p;
            float at  = bt ? 0.25f : 0.75f;
            float om  = 1.0f - pt;
            fsum += at * om * om * bce;
        }
        ((unsigned int*)g_fg)[i4]             = fgp;
        ((unsigned int*)g_fg)[i4 + NELEM/4]   = fgt;
        acc = (double)fsum;
    }
    #pragma unroll
    for (int off = 16; off > 0; off >>= 1)
        acc += __shfl_down_sync(0xffffffffu, acc, off);
    __shared__ double s[8];
    int lane = threadIdx.x & 31, w = threadIdx.x >> 5;
    if (lane == 0) s[w] = acc;
    __syncthreads();
    if (w == 0) {
        acc = (lane < (blockDim.x >> 5)) ? s[lane] : 0.0;
        #pragma unroll
        for (int off = 4; off > 0; off >>= 1)
            acc += __shfl_down_sync(0xffffffffu, acc, off);
        if (lane == 0) atomicAdd(&g_focal, acc);
    }
}

// ---------------------------------------------------------------------------
// shared-memory union-find helpers (labels monotone non-increasing)
// ---------------------------------------------------------------------------
__device__ __forceinline__ int rep_s(int* lab, int v)
{
    int curr = lab[v];
    if (curr != v) {
        int next;
        while (curr > (next = lab[curr])) {
            lab[v] = next;           // compress
            v = curr;
            curr = next;
        }
    }
    return curr;
}

__device__ __forceinline__ void unite_s(int* lab, int a, int b)
{
    int ra = rep_s(lab, a);
    int rb = rep_s(lab, b);
    while (ra != rb) {
        if (ra > rb) { int t = ra; ra = rb; rb = t; }
        int old = atomicMin(&lab[rb], ra);
        if (old == rb) return;
        rb = rep_s(lab, old);
    }
}

// ---------------------------------------------------------------------------
// per-tile local CCL: 96(D) x 8(W) x 8(H) tile, union-find in shared memory,
// then emit depth-1 global trees (fg voxels only)
// ---------------------------------------------------------------------------
__global__ __launch_bounds__(256)
void k_local()
{
    __shared__ int           lab[TVOX];
    __shared__ unsigned char fg[TVOX];

    int b   = blockIdx.x;
    int vol = b / TILES_PER_VOL;
    int t   = b % TILES_PER_VOL;
    int w0  = (t % TILES_W) * TW;
    int h0  = (t / TILES_W) * TH;
    int tid = threadIdx.x;
    int gbase = vol * NVOX;

    // load fg (coalesced along D: each (w,h) row is 96 contiguous bytes)
    for (int l = tid; l < TVOX; l += 256) {
        int d = l % HWD;
        int w = (l / HWD) % TW;
        int h = l / (HWD * TW);
        fg[l] = g_fg[gbase + (h0+h)*HWD*HWD + (w0+w)*HWD + d];
    }
    __syncthreads();

    // init labels: D-run chains
    for (int l = tid; l < TVOX; l += 256) {
        int d = l % HWD;
        lab[l] = (fg[l] && d > 0 && fg[l-1]) ? (l-1) : l;
    }
    __syncthreads();

    // local unions: +W, +H links inside tile (D-segment-start only)
    for (int l = tid; l < TVOX; l += 256) {
        if (!fg[l]) continue;
        int d = l % HWD;
        int w = (l / HWD) % TW;
        int h = l / (HWD * TW);
        bool pfg = (d > 0) && fg[l-1];
        if (w < TW-1 && fg[l + HWD]) {
            if (!(pfg && fg[l + HWD - 1]))
                unite_s(lab, l, l + HWD);
        }
        if (h < TH-1 && fg[l + HWD*TW]) {
            if (!(pfg && fg[l + HWD*TW - 1]))
                unite_s(lab, l, l + HWD*TW);
        }
    }
    __syncthreads();

    // flatten + write global labels (depth-1 trees; fg voxels only)
    for (int l = tid; l < TVOX; l += 256) {
        if (!fg[l]) continue;
        int r = lab[l];
        while (r != lab[r]) r = lab[r];
        int d  = l % HWD;
        int w  = (l / HWD) % TW;
        int h  = l / (HWD * TW);
        int rd = r % HWD;
        int rw = (r / HWD) % TW;
        int rh = r / (HWD * TW);
        int gi = gbase + (h0+h )*HWD*HWD + (w0+w )*HWD + d;
        int gr = gbase + (h0+rh)*HWD*HWD + (w0+rw)*HWD + rd;
        g_label[gi] = gr;
    }
}

// ---------------------------------------------------------------------------
// global union-find (boundary links only)
// ---------------------------------------------------------------------------
__device__ __forceinline__ int rep_g(int v)
{
    int curr = g_label[v];
    if (curr != v) {
        int next;
        while (curr > (next = g_label[curr])) {
            g_label[v] = next;
            v = curr;
            curr = next;
        }
    }
    return curr;
}

__device__ __forceinline__ void unite_g(int a, int b)
{
    int ra = rep_g(a);
    int rb = rep_g(b);
    while (ra != rb) {
        if (ra > rb) { int t = ra; ra = rb; rb = t; }
        int old = atomicMin(&g_label[rb], ra);
        if (old == rb) return;
        rb = rep_g(old);
    }
}

#define NPLANES (TILES_W - 1)               /* 11 boundary planes per axis */
#define NW_LINKS (NVOL * NPLANES * HWD*HWD) /* 811008 */

__global__ void k_boundary()
{
    int tid = blockIdx.x * blockDim.x + threadIdx.x;
    int stride, g, nbr;
    if (tid < NW_LINKS) {              // W-face links: w = 8p+7 -> w+1
        int vol = tid / (NPLANES * HWD*HWD);
        int r   = tid % (NPLANES * HWD*HWD);
        int p   = r / (HWD*HWD);
        int q   = r % (HWD*HWD);
        int h   = q / HWD;
        int d   = q % HWD;
        int w   = TW*p + (TW-1);
        g   = vol*NVOX + h*HWD*HWD + w*HWD + d;
        nbr = g + HWD;
        stride = d;                    // reuse: d for skip test
    } else if (tid < 2*NW_LINKS) {     // H-face links: h = 8p+7 -> h+1
        int u   = tid - NW_LINKS;
        int vol = u / (NPLANES * HWD*HWD);
        int r   = u % (NPLANES * HWD*HWD);
        int p   = r / (HWD*HWD);
        int q   = r % (HWD*HWD);
        int w   = q / HWD;
        int d   = q % HWD;
        int h   = TH*p + (TH-1);
        g   = vol*NVOX + h*HWD*HWD + w*HWD + d;
        nbr = g + HWD*HWD;
        stride = d;
    } else return;
    if (!g_fg[g] || !g_fg[nbr]) return;
    if (stride > 0 && g_fg[g-1] && g_fg[nbr-1]) return;  // D-segment skip
    unite_g(g, nbr);
}

// ---------------------------------------------------------------------------
// count roots per volume; 4 voxels/thread, vectorized
// ---------------------------------------------------------------------------
__global__ void k_count()
{
    int i4   = blockIdx.x * 256 + threadIdx.x;   // NTOT/4 threads
    int base = i4 * 4;
    unsigned int fgw = ((const unsigned int*)g_fg)[i4];
    int c = 0;
    if (fgw) {
        int4 l4 = ((const int4*)g_label)[i4];
        if ((fgw & 0x000000ffu) && l4.x == base  ) ++c;
        if ((fgw & 0x0000ff00u) && l4.y == base+1) ++c;
        if ((fgw & 0x00ff0000u) && l4.z == base+2) ++c;
        if ((fgw & 0xff000000u) && l4.w == base+3) ++c;
    }
    #pragma unroll
    for (int off = 16; off > 0; off >>= 1)
        c += __shfl_down_sync(0xffffffffu, c, off);
    __shared__ int s;
    if (threadIdx.x == 0) s = 0;
    __syncthreads();
    if ((threadIdx.x & 31) == 0 && c) atomicAdd(&s, c);
    __syncthreads();
    if (threadIdx.x == 0 && s > 0)
        atomicAdd(&g_counts[blockIdx.x / (NVOX/1024)], s);
}

// ---------------------------------------------------------------------------
__global__ void k_final(float* __restrict__ out)
{
    float c0 = (float)g_counts[0], c1 = (float)g_counts[1];
    float c2 = (float)g_counts[2], c3 = (float)g_counts[3];
    float t0 = (float)g_counts[4], t1 = (float)g_counts[5];
    float t2 = (float)g_counts[6], t3 = (float)g_counts[7];
    float ccp0 = 0.5f*(c0 + c2), ccp1 = 0.5f*(c1 + c3);
    float cct0 = 0.5f*(t0 + t2), cct1 = 0.5f*(t1 + t3);
    float topo = 0.5f*(fabsf(ccp0 - cct0) + fabsf(ccp1 - cct1));
    float focal = (float)(g_focal / (double)NELEM);
    out[0] = focal + 0.1f * topo;
}

// ---------------------------------------------------------------------------
extern "C" void kernel_launch(void* const* d_in, const int* in_sizes, int n_in,
                              void* d_out, int out_size)
{
    const float4* pred = (const float4*)d_in[0];
    const float4* tgt  = (const float4*)d_in[1];
    float*        out  = (float*)d_out;

    const int T = 256;
    k_zero      <<<1, 32>>>();
    k_init_focal<<<(NELEM/4 + T-1)/T, T>>>(pred, tgt);
    k_local     <<<NBLK_LOCAL, T>>>();
    k_boundary  <<<(2*NW_LINKS + T-1)/T, T>>>();
    k_count     <<<NTOT/4/T, T>>>();
    k_final     <<<1, 1>>>(out);
}

// round 4
// speedup vs baseline: 2.6311x; 1.1458x over previous
#include <cuda_runtime.h>

#define HWD   96
#define ROWB  96                /* bytes per D-row            */
#define NVOX  (96*96*96)        /* voxels per volume          */
#define NVOL  8                 /* 4 pred + 4 target          */
#define NTOT  (NVOX*NVOL)
#define NELEM (4*NVOX)

#define TW 8
#define TH 8
#define TROWS (TW*TH)           /* 64 rows per tile           */
#define TVOX (HWD*TW*TH)        /* 6144                       */
#define TILES_W (HWD/TW)        /* 12 */
#define TILES_H (HWD/TH)        /* 12 */
#define TILES_PER_VOL (TILES_W*TILES_H)  /* 144 */
#define NBLK_LOCAL (NVOL*TILES_PER_VOL)  /* 1152 */
#define NPLANES (TILES_W-1)     /* 11 boundary planes per axis */

// scratch (device globals: allocation-free per harness rules)
__device__ int            g_label[NTOT];
__device__ unsigned char  g_fg[NTOT];
__device__ double         g_focal;
__device__ int            g_counts[NVOL];

// 4 bytes (each 0/1) -> 4 bits
__device__ __forceinline__ unsigned int nib4(unsigned int v)
{
    return (v & 1u) | ((v >> 7) & 2u) | ((v >> 14) & 4u) | ((v >> 21) & 8u);
}

// build 32-bit fg mask from 32 bytes (0/1) at 4-byte-aligned pointer
__device__ __forceinline__ unsigned int mask32(const unsigned int* w)
{
    unsigned int m = 0;
    #pragma unroll
    for (int k = 0; k < 8; ++k) m |= nib4(w[k]) << (4*k);
    return m;
}

// ---------------------------------------------------------------------------
__global__ void k_zero()
{
    if (threadIdx.x == 0) g_focal = 0.0;
    if (threadIdx.x < NVOL) g_counts[threadIdx.x] = 0;
}

// ---------------------------------------------------------------------------
// fg masks (both tensors) + focal reduction; float4 + fast-math
// ---------------------------------------------------------------------------
__global__ void k_init_focal(const float4* __restrict__ pred,
                             const float4* __restrict__ tgt)
{
    int i4 = blockIdx.x * blockDim.x + threadIdx.x;
    double acc = 0.0;
    if (i4 < NELEM/4) {
        float4 x4 = pred[i4];
        float4 t4 = tgt[i4];
        const float* xs = &x4.x;
        const float* ts = &t4.x;
        unsigned int fgp = 0, fgt = 0;
        float fsum = 0.0f;
        #pragma unroll
        for (int k = 0; k < 4; ++k) {
            float x = xs[k], t = ts[k];
            bool bp = x > 0.0f;
            bool bt = t > 0.5f;
            fgp |= (bp ? 1u : 0u) << (8*k);
            fgt |= (bt ? 1u : 0u) << (8*k);
            float e   = __expf(-fabsf(x));          // e in (0,1]
            float inv = 1.0f / (1.0f + e);
            float sp  = fmaxf(x, 0.0f) + __logf(1.0f + e);
            float bce = sp - x * t;
            float p   = (x >= 0.0f) ? inv : e * inv; // sigmoid(x)
            float pt  = bt ? p : 1.0f - p;
            float at  = bt ? 0.25f : 0.75f;
            float om  = 1.0f - pt;
            fsum += at * om * om * bce;
        }
        ((unsigned int*)g_fg)[i4]           = fgp;
        ((unsigned int*)g_fg)[i4 + NELEM/4] = fgt;
        acc = (double)fsum;
    }
    #pragma unroll
    for (int off = 16; off > 0; off >>= 1)
        acc += __shfl_down_sync(0xffffffffu, acc, off);
    __shared__ double s[8];
    int lane = threadIdx.x & 31, w = threadIdx.x >> 5;
    if (lane == 0) s[w] = acc;
    __syncthreads();
    if (w == 0) {
        acc = (lane < (blockDim.x >> 5)) ? s[lane] : 0.0;
        #pragma unroll
        for (int off = 4; off > 0; off >>= 1)
            acc += __shfl_down_sync(0xffffffffu, acc, off);
        if (lane == 0) atomicAdd(&g_focal, acc);
    }
}

// ---------------------------------------------------------------------------
// shared-memory union-find (labels monotone non-increasing)
// ---------------------------------------------------------------------------
__device__ __forceinline__ int rep_s(int* lab, int v)
{
    int curr = lab[v];
    if (curr != v) {
        int next;
        while (curr > (next = lab[curr])) {
            lab[v] = next;
            v = curr;
            curr = next;
        }
    }
    return curr;
}

__device__ __forceinline__ void unite_s(int* lab, int a, int b)
{
    int ra = rep_s(lab, a);
    int rb = rep_s(lab, b);
    while (ra != rb) {
        if (ra > rb) { int t = ra; ra = rb; rb = t; }
        int old = atomicMin(&lab[rb], ra);
        if (old == rb) return;
        rb = rep_s(lab, old);
    }
}

// ---------------------------------------------------------------------------
// per-tile local CCL over D-run starts
// ---------------------------------------------------------------------------
__global__ __launch_bounds__(256)
void k_local()
{
    __shared__ unsigned char fg[TVOX];
    __shared__ int           lab[TVOX];
    __shared__ int           growbase[TROWS];

    int b   = blockIdx.x;
    int vol = b / TILES_PER_VOL;
    int t   = b % TILES_PER_VOL;
    int w0  = (t % TILES_W) * TW;
    int h0  = (t / TILES_W) * TH;
    int tid = threadIdx.x;
    int gbase = vol * NVOX;

    if (tid < TROWS)
        growbase[tid] = gbase + (h0 + tid/TW)*HWD*HWD + (w0 + tid%TW)*HWD;

    // load fg: 64 rows x 6 uint4 each
    for (int item = tid; item < TROWS*6; item += 256) {
        int row = item / 6, q = item % 6;
        int grow = gbase + (h0 + row/TW)*HWD*HWD + (w0 + row%TW)*HWD;
        ((uint4*)fg)[row*6 + q] = *(const uint4*)(g_fg + grow + 16*q);
    }
    // labels = self
    for (int item = tid; item < TVOX/4; item += 256) {
        int base = item*4;
        ((int4*)lab)[item] = make_int4(base, base+1, base+2, base+3);
    }
    __syncthreads();

    // unions: 112 row pairs (+W: 56, +H: 56) x 3 words
    for (int item = tid; item < 112*3; item += 256) {
        int pair = item / 3, j = item % 3;
        int rA, rB;
        if (pair < 56) {                       // +W: h 0..7, w 0..6
            int h = pair / 7, w = pair % 7;
            rA = h*TW + w;      rB = rA + 1;
        } else {                               // +H: h 0..6, w 0..7
            int i = pair - 56;
            int h = i / TW, w = i % TW;
            rA = h*TW + w;      rB = rA + TW;
        }
        int offA = rA * ROWB, offB = rB * ROWB;
        unsigned int mA = mask32((const unsigned int*)(fg + offA) + 8*j);
        unsigned int mB = mask32((const unsigned int*)(fg + offB) + 8*j);
        unsigned int ov = mA & mB;
        if (!ov) continue;
        unsigned int carry = 0;
        if (j > 0) carry = (fg[offA + 32*j - 1] & fg[offB + 32*j - 1]) ? 1u : 0u;
        unsigned int us = ov & ~((ov << 1) | carry);
        while (us) {
            int bbit = __ffs(us) - 1;
            us &= us - 1;
            int d = 32*j + bbit;
            int sA = offA + d; while (sA > offA && fg[sA-1]) --sA;
            int sB = offB + d; while (sB > offB && fg[sB-1]) --sB;
            unite_s(lab, sA, sB);
        }
    }
    __syncthreads();

    // emit: per run start, write global label = global(root)
    for (int item = tid; item < TROWS*3; item += 256) {
        int row = item / 3, j = item % 3;
        int off = row * ROWB;
        unsigned int m = mask32((const unsigned int*)(fg + off) + 8*j);
        if (!m) continue;
        unsigned int carry = (j > 0 && fg[off + 32*j - 1]) ? 1u : 0u;
        unsigned int st = m & ~((m << 1) | carry);
        while (st) {
            int bbit = __ffs(st) - 1;
            st &= st - 1;
            int s = off + 32*j + bbit;
            int r = lab[s];
            while (r != lab[r]) r = lab[r];
            int gs = growbase[s / ROWB] + s % ROWB;
            int gr = growbase[r / ROWB] + r % ROWB;
            g_label[gs] = gr;
        }
    }
}

// ---------------------------------------------------------------------------
// global union-find over run starts (boundary links only)
// ---------------------------------------------------------------------------
__device__ __forceinline__ int rep_g(int v)
{
    int curr = g_label[v];
    if (curr != v) {
        int next;
        while (curr > (next = g_label[curr])) {
            g_label[v] = next;
            v = curr;
            curr = next;
        }
    }
    return curr;
}

__device__ __forceinline__ void unite_g(int a, int b)
{
    int ra = rep_g(a);
    int rb = rep_g(b);
    while (ra != rb) {
        if (ra > rb) { int t = ra; ra = rb; rb = t; }
        int old = atomicMin(&g_label[rb], ra);
        if (old == rb) return;
        rb = rep_g(old);
    }
}

#define ROWS_PER_AXIS (NVOL * NPLANES * HWD)     /* 8448 row pairs per axis */
#define BITEMS (2 * ROWS_PER_AXIS * 3)           /* 50688 work items        */

__global__ void k_boundary()
{
    int tid = blockIdx.x * blockDim.x + threadIdx.x;
    if (tid >= BITEMS) return;
    int j    = tid % 3;
    int rp   = tid / 3;
    int axis = rp / ROWS_PER_AXIS;                // 0: +W faces, 1: +H faces
    int u    = rp % ROWS_PER_AXIS;
    int vol  = u / (NPLANES * HWD);
    int r2   = u % (NPLANES * HWD);
    int p    = r2 / HWD;
    int q    = r2 % HWD;                          // h for axis0, w for axis1
    int offA, offB;
    if (axis == 0) {                              // w = 8p+7 -> w+1
        int w = TW*p + (TW-1);
        offA = vol*NVOX + q*HWD*HWD + w*HWD;
        offB = offA + HWD;
    } else {                                      // h = 8p+7 -> h+1
        int h = TH*p + (TH-1);
        offA = vol*NVOX + h*HWD*HWD + q*HWD;
        offB = offA + HWD*HWD;
    }
    unsigned int mA = mask32((const unsigned int*)(g_fg + offA) + 8*j);
    unsigned int mB = mask32((const unsigned int*)(g_fg + offB) + 8*j);
    unsigned int ov = mA & mB;
    if (!ov) return;
    unsigned int carry = 0;
    if (j > 0) carry = (g_fg[offA + 32*j - 1] & g_fg[offB + 32*j - 1]) ? 1u : 0u;
    unsigned int us = ov & ~((ov << 1) | carry);
    while (us) {
        int bbit = __ffs(us) - 1;
        us &= us - 1;
        int d = 32*j + bbit;
        int sA = offA + d; while (sA > offA && g_fg[sA-1]) --sA;
        int sB = offB + d; while (sB > offB && g_fg[sB-1]) --sB;
        unite_g(sA, sB);
    }
}

// ---------------------------------------------------------------------------
// count run-start roots per volume (4 voxels/thread)
// ---------------------------------------------------------------------------
__global__ void k_count()
{
    int i4   = blockIdx.x * 256 + threadIdx.x;   // NTOT/4 threads
    int base = i4 * 4;
    unsigned int fgw = ((const unsigned int*)g_fg)[i4];
    int c = 0;
    if (fgw) {
        // previous voxel fg for each of the 4 (voxel 0's prev: byte before,
        // unless this is the first word of a row: base % 96 == 0 <=> i4%24==0)
        unsigned int prev0 = (i4 % 24 == 0) ? 0u : (unsigned int)g_fg[base - 1];
        unsigned int pw = (fgw << 8) | prev0;    // prev bytes per lane
        unsigned int starts = fgw & ~pw;         // fg && !fg_prev (bytes 0/1)
        if (starts) {
            int4 l4 = ((const int4*)g_label)[i4];
            if ((starts & 0x000000ffu) && l4.x == base  ) ++c;
            if ((starts & 0x0000ff00u) && l4.y == base+1) ++c;
            if ((starts & 0x00ff0000u) && l4.z == base+2) ++c;
            if ((starts & 0xff000000u) && l4.w == base+3) ++c;
        }
    }
    #pragma unroll
    for (int off = 16; off > 0; off >>= 1)
        c += __shfl_down_sync(0xffffffffu, c, off);
    __shared__ int s;
    if (threadIdx.x == 0) s = 0;
    __syncthreads();
    if ((threadIdx.x & 31) == 0 && c) atomicAdd(&s, c);
    __syncthreads();
    if (threadIdx.x == 0 && s > 0)
        atomicAdd(&g_counts[blockIdx.x / (NVOX/1024)], s);
}

// ---------------------------------------------------------------------------
__global__ void k_final(float* __restrict__ out)
{
    float c0 = (float)g_counts[0], c1 = (float)g_counts[1];
    float c2 = (float)g_counts[2], c3 = (float)g_counts[3];
    float t0 = (float)g_counts[4], t1 = (float)g_counts[5];
    float t2 = (float)g_counts[6], t3 = (float)g_counts[7];
    float ccp0 = 0.5f*(c0 + c2), ccp1 = 0.5f*(c1 + c3);
    float cct0 = 0.5f*(t0 + t2), cct1 = 0.5f*(t1 + t3);
    float topo = 0.5f*(fabsf(ccp0 - cct0) + fabsf(ccp1 - cct1));
    float focal = (float)(g_focal / (double)NELEM);
    out[0] = focal + 0.1f * topo;
}

// ---------------------------------------------------------------------------
extern "C" void kernel_launch(void* const* d_in, const int* in_sizes, int n_in,
                              void* d_out, int out_size)
{
    const float4* pred = (const float4*)d_in[0];
    const float4* tgt  = (const float4*)d_in[1];
    float*        out  = (float*)d_out;

    const int T = 256;
    k_zero      <<<1, 32>>>();
    k_init_focal<<<(NELEM/4 + T-1)/T, T>>>(pred, tgt);
    k_local     <<<NBLK_LOCAL, T>>>();
    k_boundary  <<<(BITEMS + T-1)/T, T>>>();
    k_count     <<<NTOT/4/T, T>>>();
    k_final     <<<1, 1>>>(out);
}